// round 11
// baseline (speedup 1.0000x reference)
#include <cuda_runtime.h>
#include <cuda_bf16.h>
#include <cstdint>

#define TB 64
#define FF 256
#define TT 512
#define HH 1024

// Column packing: (g, n) with n = jj*8 + r  ->  PC = jj*32 + g*8 + r.
// P2 CTA jj (0..127) owns PC in [32jj, 32jj+32) = all 4 gates for n in [8jj, 8jj+8).

// ---------------- device scratch ----------------
__device__ uint4 g_hA  [2][16384];          // h A-fragments ping-pong: idx4 = k8*128 + mtile*32 + lane
__device__ uint4 g_xinA[4194304];           // xin A-frags: idx4 = ((t*64 + k8)*4 + mtile)*32 + lane
__device__ uint4 g_WhB [1048576];           // Wh B-frags: idx4 = (nblk*128 + k8)*32 + lane (nblk = jj*2+nbw)
__device__ uint4 g_WxB [524288];            // Wx B-frags: idx4 = (nblk*64  + k8)*32 + lane
__device__ float g_bt  [4096];              // bias in PC order
__device__ float g_gx  [(size_t)TT * 4096 * 64];   // P1 out: [t][PC][b]
__device__ unsigned g_arrive;                      // grid-barrier counter (reset each launch)

__device__ __forceinline__ float tf32r(float v) {
    uint32_t r;
    asm("cvt.rna.tf32.f32 %0, %1;" : "=r"(r) : "f"(v));
    return __uint_as_float(r);
}
__device__ __forceinline__ float sigf(float x) { return 1.0f / (1.0f + __expf(-x)); }

__device__ __forceinline__ void mma8(float* c, const uint4& a, uint32_t b0, uint32_t b1) {
    asm volatile("mma.sync.aligned.m16n8k8.row.col.f32.tf32.tf32.f32 "
                 "{%0,%1,%2,%3}, {%4,%5,%6,%7}, {%8,%9}, {%0,%1,%2,%3};"
                 : "+f"(c[0]), "+f"(c[1]), "+f"(c[2]), "+f"(c[3])
                 : "r"(a.x), "r"(a.y), "r"(a.z), "r"(a.w), "r"(b0), "r"(b1));
}

// Fragment layouts (PTX m16n8k8): A lane=(row&7)*4+(col&3), slot=((col>>2)&1)*2+((row>>3)&1);
// B lane=n*4+(k&3), float4={t0b0,t0b1,t1b0,t1b1} per n16; C cols 2*tg+{0,1}, rows g/g+8.

// ---------------- prep: Wh -> B-fragments ----------------
__global__ __launch_bounds__(256) void prep_whB(const float* __restrict__ Wf, const float* __restrict__ Wi,
                                                const float* __restrict__ Wu, const float* __restrict__ Wo) {
    int gid = blockIdx.x * 256 + threadIdx.x;
    int n = gid & 1023, g = (gid >> 10) & 3, k = gid >> 12;
    const float* W = (g == 0) ? Wf : (g == 1) ? Wi : (g == 2) ? Wu : Wo;
    float v = tf32r(W[(size_t)(512 + k) * HH + n]);
    int jj = n >> 3, r = n & 7;
    int PC = jj * 32 + g * 8 + r;
    int nblk = PC >> 4, pcc = PC & 15;
    int tile = pcc >> 3, gg = pcc & 7;
    int lane = gg * 4 + (k & 3);
    int slot = tile * 2 + ((k >> 2) & 1);
    ((float*)g_WhB)[(size_t)(((nblk * 128) + (k >> 3)) * 32 + lane) * 4 + slot] = v;
}

// ---------------- prep: Wx -> B-fragments ----------------
__global__ __launch_bounds__(256) void prep_wxB(const float* __restrict__ Wf, const float* __restrict__ Wi,
                                                const float* __restrict__ Wu, const float* __restrict__ Wo) {
    int gid = blockIdx.x * 256 + threadIdx.x;
    int n = gid & 1023, g = (gid >> 10) & 3, k = gid >> 12;
    const float* W = (g == 0) ? Wf : (g == 1) ? Wi : (g == 2) ? Wu : Wo;
    float v = tf32r(W[(size_t)k * HH + n]);
    int jj = n >> 3, r = n & 7;
    int PC = jj * 32 + g * 8 + r;
    int nblk = PC >> 4, pcc = PC & 15;
    int tile = pcc >> 3, gg = pcc & 7;
    int lane = gg * 4 + (k & 3);
    int slot = tile * 2 + ((k >> 2) & 1);
    ((float*)g_WxB)[(size_t)(((nblk * 64) + (k >> 3)) * 32 + lane) * 4 + slot] = v;
}

// ---------------- prep: xin -> A-fragments ----------------
__global__ __launch_bounds__(256) void prep_xinA(const float* __restrict__ x, const float* __restrict__ y) {
    int gid = blockIdx.x * 256 + threadIdx.x;
    int k8 = gid & 63, b = (gid >> 6) & 63, t = gid >> 12;
    int mtile = b >> 4;
    size_t base4 = (size_t)(((t * 64 + k8) * 4) + mtile) * 32;
#pragma unroll
    for (int i = 0; i < 8; i++) {
        int kk = k8 * 8 + i;
        int f = kk >> 1;
        float v = (kk & 1) ? ((t > 0) ? y[(size_t)(b * FF + f) * TT + t - 1] : 0.0f)
                           : x[(size_t)(b * FF + f) * TT + t];
        int lane = (b & 7) * 4 + (kk & 3);
        int slot = ((kk >> 2) & 1) * 2 + ((b >> 3) & 1);
        ((float*)g_xinA)[(base4 + lane) * 4 + slot] = tf32r(v);
    }
}

// ---------------- prep: bias, zero h-frags, reset barrier ----------------
__global__ __launch_bounds__(256) void prep_misc(const float* __restrict__ bf_, const float* __restrict__ bi,
                                                 const float* __restrict__ bu, const float* __restrict__ bo) {
    int gid = blockIdx.x * 256 + threadIdx.x;
    if (gid == 0) g_arrive = 0u;
    if (gid < 16384) g_hA[0][gid] = make_uint4(0, 0, 0, 0);
    if (gid < 4096) {
        int jj = gid >> 5, w5 = gid & 31;
        int g = w5 >> 3, r = w5 & 7;
        const float* bb = (g == 0) ? bf_ : (g == 1) ? bi : (g == 2) ? bu : bo;
        g_bt[gid] = bb[jj * 8 + r];
    }
}

// ---------------- P1: gx = xin @ Wx + b.  grid (32, 512), 256 thr ----------------
__global__ __launch_bounds__(256) void p1_mma() {
    __shared__ float Ps[128][66];
    const int tid = threadIdx.x, w = tid >> 5, lane = tid & 31;
    const int j1 = blockIdx.x, t = blockIdx.y;
    const int mi = w & 1, nw = w >> 1;
    float acc[2][4][4];
#pragma unroll
    for (int a = 0; a < 2; a++)
#pragma unroll
        for (int bq = 0; bq < 4; bq++)
#pragma unroll
            for (int cq = 0; cq < 4; cq++) acc[a][bq][cq] = 0.0f;

    const size_t aBase = (size_t)t * 64 * 128 + mi * 64 + lane;
    const size_t b0Base = (size_t)(j1 * 8 + nw * 2) * 64 * 32 + lane;
    const size_t b1Base = b0Base + (size_t)64 * 32;
#pragma unroll 2
    for (int k = 0; k < 64; k++) {
        uint4 a0 = g_xinA[aBase + k * 128];
        uint4 a1 = g_xinA[aBase + k * 128 + 32];
        uint4 b0 = g_WxB[b0Base + k * 32];
        uint4 b1 = g_WxB[b1Base + k * 32];
        mma8(acc[0][0], a0, b0.x, b0.y); mma8(acc[0][1], a0, b0.z, b0.w);
        mma8(acc[0][2], a0, b1.x, b1.y); mma8(acc[0][3], a0, b1.z, b1.w);
        mma8(acc[1][0], a1, b0.x, b0.y); mma8(acc[1][1], a1, b0.z, b0.w);
        mma8(acc[1][2], a1, b1.x, b1.y); mma8(acc[1][3], a1, b1.z, b1.w);
    }
    const int g = lane >> 2, tg = lane & 3;
#pragma unroll
    for (int tm = 0; tm < 2; tm++)
#pragma unroll
        for (int tn = 0; tn < 4; tn++) {
            int rb = mi * 32 + tm * 16 + g;
            int cb = nw * 32 + tn * 8 + 2 * tg;
            Ps[cb][rb]         = acc[tm][tn][0];
            Ps[cb + 1][rb]     = acc[tm][tn][1];
            Ps[cb][rb + 8]     = acc[tm][tn][2];
            Ps[cb + 1][rb + 8] = acc[tm][tn][3];
        }
    __syncthreads();
    float* gxp = g_gx + ((size_t)t * 4096 + j1 * 128) * 64;
    for (int i = tid; i < 8192; i += 256) {
        int pcl = i >> 6, b = i & 63;
        gxp[(size_t)pcl * 64 + b] = Ps[pcl][b] + g_bt[j1 * 128 + pcl];
    }
}

// ---------------- P2: persistent LSTM. grid 128 (co-resident), 256 thr ----------------
// Warp (kh, mq). Wh + c + 32-step h staging all smem-resident; one grid barrier/step;
// software-pipelined A loads; h flushed straight to out every 32 steps.
__global__ __launch_bounds__(256) void lstm_persist(float* __restrict__ out) {
    extern __shared__ uint4 smemB[];            // [0, 8192): Wh slice (128KB)
    float* hbuf = (float*)(smemB + 8192);       // 512*33 floats (66KB): [(r*64+b)*33 + (t&31)]
    __shared__ float Ps[2][32][66];
    __shared__ float c_s[512];
    const int tid = threadIdx.x, w = tid >> 5, lane = tid & 31;
    const int jj = blockIdx.x;
    const int kh = w & 1, mq = w >> 1;
    const int g = lane >> 2, tg = lane & 3;

    {   // load Wh slice into smem once
        const uint4* src = g_WhB + (size_t)jj * 2 * 128 * 32;
        for (int i = tid; i < 8192; i += 256) smemB[i] = src[i];
    }
    for (int i = tid; i < 512; i += 256) c_s[i] = 0.0f;
    __syncthreads();

    for (int t = 0; t < TT; t++) {
        const int par = t & 1;
        float gxr[8];
        const float* gxp = g_gx + ((size_t)t * 4096 + jj * 32) * 64;
#pragma unroll
        for (int i = 0; i < 8; i++) gxr[i] = gxp[tid + i * 256];

        float acc[2][2][4];
#pragma unroll
        for (int a = 0; a < 2; a++)
#pragma unroll
            for (int bq = 0; bq < 2; bq++)
#pragma unroll
                for (int cq = 0; cq < 4; cq++) acc[a][bq][cq] = 0.0f;

        // software-pipelined mainloop: 8 groups of 8 k-iters, A double-buffered
        const uint4* __restrict__ Abase = g_hA[par] + (size_t)(kh * 64) * 128 + mq * 32 + lane;
        uint4 a_cur[8], a_nxt[8];
#pragma unroll
        for (int i = 0; i < 8; i++) a_cur[i] = Abase[(size_t)i * 128];
#pragma unroll
        for (int kg = 0; kg < 8; kg++) {
            if (kg < 7) {
#pragma unroll
                for (int i = 0; i < 8; i++) a_nxt[i] = Abase[(size_t)((kg + 1) * 8 + i) * 128];
            }
#pragma unroll
            for (int i = 0; i < 8; i++) {
                int k = kh * 64 + kg * 8 + i;
                uint4 b0 = smemB[k * 32 + lane];
                uint4 b1 = smemB[4096 + k * 32 + lane];
                mma8(acc[0][0], a_cur[i], b0.x, b0.y); mma8(acc[0][1], a_cur[i], b0.z, b0.w);
                mma8(acc[1][0], a_cur[i], b1.x, b1.y); mma8(acc[1][1], a_cur[i], b1.z, b1.w);
            }
#pragma unroll
            for (int i = 0; i < 8; i++) a_cur[i] = a_nxt[i];
        }

#pragma unroll
        for (int nb = 0; nb < 2; nb++)
#pragma unroll
            for (int tn = 0; tn < 2; tn++) {
                int rb = mq * 16 + g;
                int cb = nb * 16 + tn * 8 + 2 * tg;
                Ps[kh][cb][rb]         = acc[nb][tn][0];
                Ps[kh][cb + 1][rb]     = acc[nb][tn][1];
                Ps[kh][cb][rb + 8]     = acc[nb][tn][2];
                Ps[kh][cb + 1][rb + 8] = acc[nb][tn][3];
            }
        __syncthreads();

        // epilogue: 512 cells, 2 per thread (ownership stable across t)
        float* hAn = (float*)g_hA[par ^ 1];
#pragma unroll
        for (int it = 0; it < 2; it++) {
            int idx = tid + it * 256;
            int r = idx >> 6, b = idx & 63;
            float p[4];
#pragma unroll
            for (int gg = 0; gg < 4; gg++)
                p[gg] = Ps[0][gg * 8 + r][b] + Ps[1][gg * 8 + r][b] + gxr[2 * gg + it];
            float ff = sigf(p[0]), ii = sigf(p[1]), uu = tanhf(p[2]), oo = sigf(p[3]);
            float cn = c_s[idx] * ff + ii * uu;
            c_s[idx] = cn;
            float h = oo * tanhf(cn);
            hbuf[idx * 33 + (t & 31)] = h;
            int lane2 = (b & 7) * 4 + (r & 3);
            int slot  = ((r >> 2) & 1) * 2 + ((b >> 3) & 1);
            int mtile = b >> 4;
            hAn[(size_t)(jj * 128 + mtile * 32 + lane2) * 4 + slot] = tf32r(h);
        }

        // flush 32 finished timesteps straight to out[b][n][t0..t0+32)
        if ((t & 31) == 31) {
            int t0 = t - 31;
#pragma unroll
            for (int it = 0; it < 2; it++) {
                int idx = tid + it * 256;
                int r = idx >> 6, b = idx & 63;
                const float* src = &hbuf[idx * 33];
                float* dst = out + ((size_t)b * HH + jj * 8 + r) * TT + t0;
#pragma unroll
                for (int q = 0; q < 8; q++) {
                    float4 v = make_float4(src[4 * q], src[4 * q + 1], src[4 * q + 2], src[4 * q + 3]);
                    *(float4*)(dst + 4 * q) = v;
                }
            }
        }

        // grid barrier (monotone counter; 128 CTAs co-resident)
        __threadfence();
        __syncthreads();
        if (tid == 0) {
            atomicAdd(&g_arrive, 1u);
            unsigned target = 128u * (unsigned)(t + 1);
            while (*(volatile unsigned*)&g_arrive < target) { }
            __threadfence();
        }
        __syncthreads();
    }

    // c_fin -> out tail
    for (int i = tid; i < 512; i += 256) {
        int r = i >> 6, b = i & 63;
        out[(size_t)TB * HH * TT + b * HH + jj * 8 + r] = c_s[i];
    }
}

// ---------------- launch ----------------
extern "C" void kernel_launch(void* const* d_in, const int* in_sizes, int n_in,
                              void* d_out, int out_size) {
    const float* x   = (const float*)d_in[0];
    const float* y   = (const float*)d_in[1];
    // d_in[2] = subject_id (unused in 'none' mode)
    const float* Wf  = (const float*)d_in[3];
    const float* bf_ = (const float*)d_in[4];
    const float* Wi  = (const float*)d_in[5];
    const float* bi  = (const float*)d_in[6];
    const float* Wu  = (const float*)d_in[7];
    const float* bu  = (const float*)d_in[8];
    const float* Wo  = (const float*)d_in[9];
    const float* bo  = (const float*)d_in[10];
    float* out = (float*)d_out;

    const int P2_SMEM = 8192 * 16 + 512 * 33 * 4;   // Wh slice + hbuf = 198656 B
    cudaFuncSetAttribute(lstm_persist, cudaFuncAttributeMaxDynamicSharedMemorySize, P2_SMEM);

    prep_whB <<<16384, 256>>>(Wf, Wi, Wu, Wo);
    prep_wxB <<<8192, 256>>>(Wf, Wi, Wu, Wo);
    prep_xinA<<<8192, 256>>>(x, y);
    prep_misc<<<256, 256>>>(bf_, bi, bu, bo);

    p1_mma<<<dim3(32, 512), 256>>>();

    lstm_persist<<<128, 256, P2_SMEM>>>(out);
}

// round 12
// speedup vs baseline: 1.2053x; 1.2053x over previous
#include <cuda_runtime.h>
#include <cuda_bf16.h>
#include <cstdint>

#define TB 64
#define FF 256
#define TT 512
#define HH 1024

// Column packing: (g, n) with n = jj*8 + r  ->  PC = jj*32 + g*8 + r.
// P2 CTA jj (0..127) owns PC in [32jj, 32jj+32) = all 4 gates for n in [8jj, 8jj+8).

// ---------------- device scratch ----------------
__device__ uint4 g_hA  [2][16384];          // h A-fragments ping-pong: idx4 = k8*128 + mtile*32 + lane
__device__ uint4 g_xinA[4194304];           // xin A-frags: idx4 = ((t*64 + k8)*4 + mtile)*32 + lane
__device__ uint4 g_WhB [1048576];           // Wh B-frags: idx4 = (nblk*128 + k8)*32 + lane (nblk = jj*2+nbw)
__device__ uint4 g_WxB [524288];            // Wx B-frags: idx4 = (nblk*64  + k8)*32 + lane
__device__ float g_bt  [4096];              // bias in PC order
__device__ float g_gx  [(size_t)TT * 4096 * 64];   // P1 out: [t][PC][b]
__device__ unsigned g_arrive;                      // grid-barrier counter (reset each launch)

__device__ __forceinline__ float tf32r(float v) {
    uint32_t r;
    asm("cvt.rna.tf32.f32 %0, %1;" : "=r"(r) : "f"(v));
    return __uint_as_float(r);
}
__device__ __forceinline__ float sigf(float x) { return 1.0f / (1.0f + __expf(-x)); }

__device__ __forceinline__ void mma8(float* c, const uint4& a, uint32_t b0, uint32_t b1) {
    asm volatile("mma.sync.aligned.m16n8k8.row.col.f32.tf32.tf32.f32 "
                 "{%0,%1,%2,%3}, {%4,%5,%6,%7}, {%8,%9}, {%0,%1,%2,%3};"
                 : "+f"(c[0]), "+f"(c[1]), "+f"(c[2]), "+f"(c[3])
                 : "r"(a.x), "r"(a.y), "r"(a.z), "r"(a.w), "r"(b0), "r"(b1));
}

// Fragment layouts (PTX m16n8k8): A lane=(row&7)*4+(col&3), slot=((col>>2)&1)*2+((row>>3)&1);
// B lane=n*4+(k&3), float4={t0b0,t0b1,t1b0,t1b1} per n16; C cols 2*tg+{0,1}, rows g/g+8.

// ---------------- prep: Wh -> B-fragments ----------------
__global__ __launch_bounds__(256) void prep_whB(const float* __restrict__ Wf, const float* __restrict__ Wi,
                                                const float* __restrict__ Wu, const float* __restrict__ Wo) {
    int gid = blockIdx.x * 256 + threadIdx.x;
    int n = gid & 1023, g = (gid >> 10) & 3, k = gid >> 12;
    const float* W = (g == 0) ? Wf : (g == 1) ? Wi : (g == 2) ? Wu : Wo;
    float v = tf32r(W[(size_t)(512 + k) * HH + n]);
    int jj = n >> 3, r = n & 7;
    int PC = jj * 32 + g * 8 + r;
    int nblk = PC >> 4, pcc = PC & 15;
    int tile = pcc >> 3, gg = pcc & 7;
    int lane = gg * 4 + (k & 3);
    int slot = tile * 2 + ((k >> 2) & 1);
    ((float*)g_WhB)[(size_t)(((nblk * 128) + (k >> 3)) * 32 + lane) * 4 + slot] = v;
}

// ---------------- prep: Wx -> B-fragments ----------------
__global__ __launch_bounds__(256) void prep_wxB(const float* __restrict__ Wf, const float* __restrict__ Wi,
                                                const float* __restrict__ Wu, const float* __restrict__ Wo) {
    int gid = blockIdx.x * 256 + threadIdx.x;
    int n = gid & 1023, g = (gid >> 10) & 3, k = gid >> 12;
    const float* W = (g == 0) ? Wf : (g == 1) ? Wi : (g == 2) ? Wu : Wo;
    float v = tf32r(W[(size_t)k * HH + n]);
    int jj = n >> 3, r = n & 7;
    int PC = jj * 32 + g * 8 + r;
    int nblk = PC >> 4, pcc = PC & 15;
    int tile = pcc >> 3, gg = pcc & 7;
    int lane = gg * 4 + (k & 3);
    int slot = tile * 2 + ((k >> 2) & 1);
    ((float*)g_WxB)[(size_t)(((nblk * 64) + (k >> 3)) * 32 + lane) * 4 + slot] = v;
}

// ---------------- prep: xin -> A-fragments ----------------
__global__ __launch_bounds__(256) void prep_xinA(const float* __restrict__ x, const float* __restrict__ y) {
    int gid = blockIdx.x * 256 + threadIdx.x;
    int k8 = gid & 63, b = (gid >> 6) & 63, t = gid >> 12;
    int mtile = b >> 4;
    size_t base4 = (size_t)(((t * 64 + k8) * 4) + mtile) * 32;
#pragma unroll
    for (int i = 0; i < 8; i++) {
        int kk = k8 * 8 + i;
        int f = kk >> 1;
        float v = (kk & 1) ? ((t > 0) ? y[(size_t)(b * FF + f) * TT + t - 1] : 0.0f)
                           : x[(size_t)(b * FF + f) * TT + t];
        int lane = (b & 7) * 4 + (kk & 3);
        int slot = ((kk >> 2) & 1) * 2 + ((b >> 3) & 1);
        ((float*)g_xinA)[(base4 + lane) * 4 + slot] = tf32r(v);
    }
}

// ---------------- prep: bias, zero h-frags, reset barrier ----------------
__global__ __launch_bounds__(256) void prep_misc(const float* __restrict__ bf_, const float* __restrict__ bi,
                                                 const float* __restrict__ bu, const float* __restrict__ bo) {
    int gid = blockIdx.x * 256 + threadIdx.x;
    if (gid == 0) g_arrive = 0u;
    if (gid < 16384) g_hA[0][gid] = make_uint4(0, 0, 0, 0);
    if (gid < 4096) {
        int jj = gid >> 5, w5 = gid & 31;
        int g = w5 >> 3, r = w5 & 7;
        const float* bb = (g == 0) ? bf_ : (g == 1) ? bi : (g == 2) ? bu : bo;
        g_bt[gid] = bb[jj * 8 + r];
    }
}

// ---------------- P1: gx = xin @ Wx + b.  grid (32, 512), 256 thr ----------------
__global__ __launch_bounds__(256) void p1_mma() {
    __shared__ float Ps[128][66];
    const int tid = threadIdx.x, w = tid >> 5, lane = tid & 31;
    const int j1 = blockIdx.x, t = blockIdx.y;
    const int mi = w & 1, nw = w >> 1;
    float acc[2][4][4];
#pragma unroll
    for (int a = 0; a < 2; a++)
#pragma unroll
        for (int bq = 0; bq < 4; bq++)
#pragma unroll
            for (int cq = 0; cq < 4; cq++) acc[a][bq][cq] = 0.0f;

    const size_t aBase = (size_t)t * 64 * 128 + mi * 64 + lane;
    const size_t b0Base = (size_t)(j1 * 8 + nw * 2) * 64 * 32 + lane;
    const size_t b1Base = b0Base + (size_t)64 * 32;
#pragma unroll 2
    for (int k = 0; k < 64; k++) {
        uint4 a0 = g_xinA[aBase + k * 128];
        uint4 a1 = g_xinA[aBase + k * 128 + 32];
        uint4 b0 = g_WxB[b0Base + k * 32];
        uint4 b1 = g_WxB[b1Base + k * 32];
        mma8(acc[0][0], a0, b0.x, b0.y); mma8(acc[0][1], a0, b0.z, b0.w);
        mma8(acc[0][2], a0, b1.x, b1.y); mma8(acc[0][3], a0, b1.z, b1.w);
        mma8(acc[1][0], a1, b0.x, b0.y); mma8(acc[1][1], a1, b0.z, b0.w);
        mma8(acc[1][2], a1, b1.x, b1.y); mma8(acc[1][3], a1, b1.z, b1.w);
    }
    const int g = lane >> 2, tg = lane & 3;
#pragma unroll
    for (int tm = 0; tm < 2; tm++)
#pragma unroll
        for (int tn = 0; tn < 4; tn++) {
            int rb = mi * 32 + tm * 16 + g;
            int cb = nw * 32 + tn * 8 + 2 * tg;
            Ps[cb][rb]         = acc[tm][tn][0];
            Ps[cb + 1][rb]     = acc[tm][tn][1];
            Ps[cb][rb + 8]     = acc[tm][tn][2];
            Ps[cb + 1][rb + 8] = acc[tm][tn][3];
        }
    __syncthreads();
    float* gxp = g_gx + ((size_t)t * 4096 + j1 * 128) * 64;
    for (int i = tid; i < 8192; i += 256) {
        int pcl = i >> 6, b = i & 63;
        gxp[(size_t)pcl * 64 + b] = Ps[pcl][b] + g_bt[j1 * 128 + pcl];
    }
}

// ---------------- P2: persistent LSTM. grid 128, 512 thr (16 warps) ----------------
// Warp (kq 0..3, mq 0..3): K-quarter x m16 tile, full n32. 4 warps/SMSP for latency cover.
// Split barrier: arrive after h-writes; 16-step output flush between arrive and wait.
__global__ __launch_bounds__(512) void lstm_persist(float* __restrict__ out) {
    extern __shared__ uint4 smemB[];            // [0, 8192): Wh slice (128KB)
    float* hbuf = (float*)(smemB + 8192);       // 512*17 floats (34KB): [tid*17 + (t&15)]
    __shared__ float Ps[4][32][66];             // kq partials
    __shared__ float c_s[512];
    const int tid = threadIdx.x, w = tid >> 5, lane = tid & 31;
    const int jj = blockIdx.x;
    const int kq = w & 3, mq = w >> 2;
    const int g = lane >> 2, tg = lane & 3;
    const int r_ep = tid >> 6, b_ep = tid & 63;    // epilogue cell (1 per thread)

    {   // load Wh slice into smem once
        const uint4* src = g_WhB + (size_t)jj * 8192;
        for (int i = tid; i < 8192; i += 512) smemB[i] = src[i];
    }
    c_s[tid] = 0.0f;
    __syncthreads();

    for (int t = 0; t < TT; t++) {
        const int par = t & 1;
        float gxr[4];
        const float* gxp = g_gx + ((size_t)t * 4096 + jj * 32) * 64;
#pragma unroll
        for (int i = 0; i < 4; i++) gxr[i] = gxp[tid + i * 512];   // gx[gg*512 + tid]

        float acc[2][2][4];
#pragma unroll
        for (int a = 0; a < 2; a++)
#pragma unroll
            for (int bq = 0; bq < 2; bq++)
#pragma unroll
                for (int cq = 0; cq < 4; cq++) acc[a][bq][cq] = 0.0f;

        const uint4* __restrict__ A = g_hA[par] + (size_t)(kq * 32) * 128 + mq * 32 + lane;
#pragma unroll 8
        for (int kk = 0; kk < 32; kk++) {
            uint4 a = A[(size_t)kk * 128];
            int k = kq * 32 + kk;
            uint4 b0 = smemB[k * 32 + lane];
            uint4 b1 = smemB[4096 + k * 32 + lane];
            mma8(acc[0][0], a, b0.x, b0.y); mma8(acc[0][1], a, b0.z, b0.w);
            mma8(acc[1][0], a, b1.x, b1.y); mma8(acc[1][1], a, b1.z, b1.w);
        }
#pragma unroll
        for (int nb = 0; nb < 2; nb++)
#pragma unroll
            for (int tn = 0; tn < 2; tn++) {
                int rb = mq * 16 + g;
                int cb = nb * 16 + tn * 8 + 2 * tg;
                Ps[kq][cb][rb]         = acc[nb][tn][0];
                Ps[kq][cb + 1][rb]     = acc[nb][tn][1];
                Ps[kq][cb][rb + 8]     = acc[nb][tn][2];
                Ps[kq][cb + 1][rb + 8] = acc[nb][tn][3];
            }
        __syncthreads();

        // epilogue: 1 cell per thread
        {
            float p[4];
#pragma unroll
            for (int gg = 0; gg < 4; gg++) {
                int pcl = gg * 8 + r_ep;
                p[gg] = Ps[0][pcl][b_ep] + Ps[1][pcl][b_ep] + Ps[2][pcl][b_ep] + Ps[3][pcl][b_ep]
                      + gxr[gg];
            }
            float ff = sigf(p[0]), ii = sigf(p[1]), uu = tanhf(p[2]), oo = sigf(p[3]);
            float cn = c_s[tid] * ff + ii * uu;
            c_s[tid] = cn;
            float h = oo * tanhf(cn);
            hbuf[tid * 17 + (t & 15)] = h;
            float* hAn = (float*)g_hA[par ^ 1];
            int lane2 = (b_ep & 7) * 4 + (r_ep & 3);
            int slot  = ((r_ep >> 2) & 1) * 2 + ((b_ep >> 3) & 1);
            int mtile = b_ep >> 4;
            hAn[(size_t)(jj * 128 + mtile * 32 + lane2) * 4 + slot] = tf32r(h);
        }

        // split barrier: arrive, then flush (overlaps other CTAs' arrival), then wait
        __threadfence();
        __syncthreads();
        if (tid == 0) atomicAdd(&g_arrive, 1u);

        if ((t & 15) == 15) {
            int t0 = t - 15;
            const float* src = &hbuf[tid * 17];
            float* dst = out + ((size_t)b_ep * HH + jj * 8 + r_ep) * TT + t0;
#pragma unroll
            for (int q = 0; q < 4; q++) {
                float4 v = make_float4(src[4 * q], src[4 * q + 1], src[4 * q + 2], src[4 * q + 3]);
                *(float4*)(dst + 4 * q) = v;
            }
        }

        if (tid == 0) {
            unsigned target = 128u * (unsigned)(t + 1);
            while (*(volatile unsigned*)&g_arrive < target) { }
            __threadfence();
        }
        __syncthreads();
    }

    // c_fin -> out tail
    out[(size_t)TB * HH * TT + b_ep * HH + jj * 8 + r_ep] = c_s[tid];
}

// ---------------- launch ----------------
extern "C" void kernel_launch(void* const* d_in, const int* in_sizes, int n_in,
                              void* d_out, int out_size) {
    const float* x   = (const float*)d_in[0];
    const float* y   = (const float*)d_in[1];
    // d_in[2] = subject_id (unused in 'none' mode)
    const float* Wf  = (const float*)d_in[3];
    const float* bf_ = (const float*)d_in[4];
    const float* Wi  = (const float*)d_in[5];
    const float* bi  = (const float*)d_in[6];
    const float* Wu  = (const float*)d_in[7];
    const float* bu  = (const float*)d_in[8];
    const float* Wo  = (const float*)d_in[9];
    const float* bo  = (const float*)d_in[10];
    float* out = (float*)d_out;

    const int P2_SMEM = 8192 * 16 + 512 * 17 * 4;   // Wh + hbuf = 165888 B dynamic
    cudaFuncSetAttribute(lstm_persist, cudaFuncAttributeMaxDynamicSharedMemorySize, P2_SMEM);

    prep_whB <<<16384, 256>>>(Wf, Wi, Wu, Wo);
    prep_wxB <<<8192, 256>>>(Wf, Wi, Wu, Wo);
    prep_xinA<<<8192, 256>>>(x, y);
    prep_misc<<<256, 256>>>(bf_, bi, bu, bo);

    p1_mma<<<dim3(32, 512), 256>>>();

    lstm_persist<<<128, 512, P2_SMEM>>>(out);
}

// round 15
// speedup vs baseline: 1.2409x; 1.0295x over previous
#include <cuda_runtime.h>
#include <cuda_bf16.h>
#include <cstdint>

#define TB 64
#define FF 256
#define TT 512
#define HH 1024

// Column packing: (g, n) with n = jj*8 + r  ->  PC = jj*32 + g*8 + r.
// P2 CTA jj (0..127) owns PC in [32jj, 32jj+32) = all 4 gates for n in [8jj, 8jj+8).

// ---------------- device scratch ----------------
__device__ uint4 g_hA  [2][16384];          // h A-fragments ping-pong: idx4 = k8*128 + mtile*32 + lane
__device__ uint4 g_xinA[4194304];           // xin A-frags: idx4 = ((t*64 + k8)*4 + mtile)*32 + lane
__device__ uint4 g_WhB [1048576];           // Wh B-frags: idx4 = (nblk*128 + k8)*32 + lane (nblk = jj*2+nbw)
__device__ uint4 g_WxB [524288];            // Wx B-frags: idx4 = (nblk*64  + k8)*32 + lane
__device__ float g_bt  [4096];              // bias in PC order
__device__ float g_gx  [(size_t)TT * 4096 * 64];   // P1 out: [t][PC][b]
__device__ unsigned g_arrive;                      // grid-barrier counter (reset each launch)

__device__ __forceinline__ float tf32r(float v) {
    uint32_t r;
    asm("cvt.rna.tf32.f32 %0, %1;" : "=r"(r) : "f"(v));
    return __uint_as_float(r);
}
__device__ __forceinline__ float sigf(float x) { return 1.0f / (1.0f + __expf(-x)); }

__device__ __forceinline__ void mma8(float* c, const uint4& a, uint32_t b0, uint32_t b1) {
    asm volatile("mma.sync.aligned.m16n8k8.row.col.f32.tf32.tf32.f32 "
                 "{%0,%1,%2,%3}, {%4,%5,%6,%7}, {%8,%9}, {%0,%1,%2,%3};"
                 : "+f"(c[0]), "+f"(c[1]), "+f"(c[2]), "+f"(c[3])
                 : "r"(a.x), "r"(a.y), "r"(a.z), "r"(a.w), "r"(b0), "r"(b1));
}

// Fragment layouts (PTX m16n8k8): A lane=(row&7)*4+(col&3), slot=((col>>2)&1)*2+((row>>3)&1);
// B lane=n*4+(k&3), float4={t0b0,t0b1,t1b0,t1b1} per n16; C cols 2*tg+{0,1}, rows g/g+8.

// ---------------- prep: Wh -> B-fragments ----------------
__global__ __launch_bounds__(256) void prep_whB(const float* __restrict__ Wf, const float* __restrict__ Wi,
                                                const float* __restrict__ Wu, const float* __restrict__ Wo) {
    int gid = blockIdx.x * 256 + threadIdx.x;
    int n = gid & 1023, g = (gid >> 10) & 3, k = gid >> 12;
    const float* W = (g == 0) ? Wf : (g == 1) ? Wi : (g == 2) ? Wu : Wo;
    float v = tf32r(W[(size_t)(512 + k) * HH + n]);
    int jj = n >> 3, r = n & 7;
    int PC = jj * 32 + g * 8 + r;
    int nblk = PC >> 4, pcc = PC & 15;
    int tile = pcc >> 3, gg = pcc & 7;
    int lane = gg * 4 + (k & 3);
    int slot = tile * 2 + ((k >> 2) & 1);
    ((float*)g_WhB)[(size_t)(((nblk * 128) + (k >> 3)) * 32 + lane) * 4 + slot] = v;
}

// ---------------- prep: Wx -> B-fragments ----------------
__global__ __launch_bounds__(256) void prep_wxB(const float* __restrict__ Wf, const float* __restrict__ Wi,
                                                const float* __restrict__ Wu, const float* __restrict__ Wo) {
    int gid = blockIdx.x * 256 + threadIdx.x;
    int n = gid & 1023, g = (gid >> 10) & 3, k = gid >> 12;
    const float* W = (g == 0) ? Wf : (g == 1) ? Wi : (g == 2) ? Wu : Wo;
    float v = tf32r(W[(size_t)k * HH + n]);
    int jj = n >> 3, r = n & 7;
    int PC = jj * 32 + g * 8 + r;
    int nblk = PC >> 4, pcc = PC & 15;
    int tile = pcc >> 3, gg = pcc & 7;
    int lane = gg * 4 + (k & 3);
    int slot = tile * 2 + ((k >> 2) & 1);
    ((float*)g_WxB)[(size_t)(((nblk * 64) + (k >> 3)) * 32 + lane) * 4 + slot] = v;
}

// ---------------- prep: xin -> A-fragments ----------------
__global__ __launch_bounds__(256) void prep_xinA(const float* __restrict__ x, const float* __restrict__ y) {
    int gid = blockIdx.x * 256 + threadIdx.x;
    int k8 = gid & 63, b = (gid >> 6) & 63, t = gid >> 12;
    int mtile = b >> 4;
    size_t base4 = (size_t)(((t * 64 + k8) * 4) + mtile) * 32;
#pragma unroll
    for (int i = 0; i < 8; i++) {
        int kk = k8 * 8 + i;
        int f = kk >> 1;
        float v = (kk & 1) ? ((t > 0) ? y[(size_t)(b * FF + f) * TT + t - 1] : 0.0f)
                           : x[(size_t)(b * FF + f) * TT + t];
        int lane = (b & 7) * 4 + (kk & 3);
        int slot = ((kk >> 2) & 1) * 2 + ((b >> 3) & 1);
        ((float*)g_xinA)[(base4 + lane) * 4 + slot] = tf32r(v);
    }
}

// ---------------- prep: bias, zero h-frags, reset barrier ----------------
__global__ __launch_bounds__(256) void prep_misc(const float* __restrict__ bf_, const float* __restrict__ bi,
                                                 const float* __restrict__ bu, const float* __restrict__ bo) {
    int gid = blockIdx.x * 256 + threadIdx.x;
    if (gid == 0) g_arrive = 0u;
    if (gid < 16384) g_hA[0][gid] = make_uint4(0, 0, 0, 0);
    if (gid < 4096) {
        int jj = gid >> 5, w5 = gid & 31;
        int g = w5 >> 3, r = w5 & 7;
        const float* bb = (g == 0) ? bf_ : (g == 1) ? bi : (g == 2) ? bu : bo;
        g_bt[gid] = bb[jj * 8 + r];
    }
}

// ---------------- P1: gx = xin @ Wx + b.  grid (32, 512), 256 thr ----------------
__global__ __launch_bounds__(256) void p1_mma() {
    __shared__ float Ps[128][66];
    const int tid = threadIdx.x, w = tid >> 5, lane = tid & 31;
    const int j1 = blockIdx.x, t = blockIdx.y;
    const int mi = w & 1, nw = w >> 1;
    float acc[2][4][4];
#pragma unroll
    for (int a = 0; a < 2; a++)
#pragma unroll
        for (int bq = 0; bq < 4; bq++)
#pragma unroll
            for (int cq = 0; cq < 4; cq++) acc[a][bq][cq] = 0.0f;

    const size_t aBase = (size_t)t * 64 * 128 + mi * 64 + lane;
    const size_t b0Base = (size_t)(j1 * 8 + nw * 2) * 64 * 32 + lane;
    const size_t b1Base = b0Base + (size_t)64 * 32;
#pragma unroll 2
    for (int k = 0; k < 64; k++) {
        uint4 a0 = g_xinA[aBase + k * 128];
        uint4 a1 = g_xinA[aBase + k * 128 + 32];
        uint4 b0 = g_WxB[b0Base + k * 32];
        uint4 b1 = g_WxB[b1Base + k * 32];
        mma8(acc[0][0], a0, b0.x, b0.y); mma8(acc[0][1], a0, b0.z, b0.w);
        mma8(acc[0][2], a0, b1.x, b1.y); mma8(acc[0][3], a0, b1.z, b1.w);
        mma8(acc[1][0], a1, b0.x, b0.y); mma8(acc[1][1], a1, b0.z, b0.w);
        mma8(acc[1][2], a1, b1.x, b1.y); mma8(acc[1][3], a1, b1.z, b1.w);
    }
    const int g = lane >> 2, tg = lane & 3;
#pragma unroll
    for (int tm = 0; tm < 2; tm++)
#pragma unroll
        for (int tn = 0; tn < 4; tn++) {
            int rb = mi * 32 + tm * 16 + g;
            int cb = nw * 32 + tn * 8 + 2 * tg;
            Ps[cb][rb]         = acc[tm][tn][0];
            Ps[cb + 1][rb]     = acc[tm][tn][1];
            Ps[cb][rb + 8]     = acc[tm][tn][2];
            Ps[cb + 1][rb + 8] = acc[tm][tn][3];
        }
    __syncthreads();
    float* gxp = g_gx + ((size_t)t * 4096 + j1 * 128) * 64;
    for (int i = tid; i < 8192; i += 256) {
        int pcl = i >> 6, b = i & 63;
        gxp[(size_t)pcl * 64 + b] = Ps[pcl][b] + g_bt[j1 * 128 + pcl];
    }
}

// ---------------- P2: persistent LSTM. grid 128, 512 thr (16 warps) ----------------
// Warp (kq 0..7, mh 0..1): K-eighth (16 k8) x m32 (2 A-tiles), full n32.
// m32 per warp halves smem B traffic. All big buffers in dynamic smem (static cap 48KB).
// Dynamic layout (uint4 base): [0,8192) Wh; then hbuf 512*9 f32; Ps 8*32*68 f32; c_s 512 f32.
__global__ __launch_bounds__(512) void lstm_persist(float* __restrict__ out) {
    extern __shared__ uint4 smemB[];
    float* hbuf = (float*)(smemB + 8192);               // 512*9  = 4608 f32
    float* PsF  = hbuf + 512 * 9;                       // 8*32*68 = 17408 f32
    float* c_s  = PsF + 8 * 32 * 68;                    // 512 f32
#define PS(q, c, r) PsF[((q) * 32 + (c)) * 68 + (r)]
    const int tid = threadIdx.x, w = tid >> 5, lane = tid & 31;
    const int jj = blockIdx.x;
    const int kq = w & 7, mh = w >> 3;
    const int g = lane >> 2, tg = lane & 3;
    const int r_ep = tid >> 6, b_ep = tid & 63;    // epilogue cell (1 per thread)

    {   // load Wh slice into smem once
        const uint4* src = g_WhB + (size_t)jj * 8192;
        for (int i = tid; i < 8192; i += 512) smemB[i] = src[i];
    }
    c_s[tid] = 0.0f;
    __syncthreads();

    for (int t = 0; t < TT; t++) {
        const int par = t & 1;
        float gxr[4];
        const float* gxp = g_gx + ((size_t)t * 4096 + jj * 32) * 64;
#pragma unroll
        for (int i = 0; i < 4; i++) gxr[i] = gxp[tid + i * 512];   // gx[gg*512 + tid]

        float acc[2][2][2][4];      // [a-tile][nb][tn][4]
#pragma unroll
        for (int a = 0; a < 2; a++)
#pragma unroll
            for (int nb = 0; nb < 2; nb++)
#pragma unroll
                for (int tn = 0; tn < 2; tn++)
#pragma unroll
                    for (int cq = 0; cq < 4; cq++) acc[a][nb][tn][cq] = 0.0f;

        const uint4* __restrict__ A = g_hA[par] + (size_t)(kq * 16) * 128 + mh * 64 + lane;
#pragma unroll 4
        for (int kk = 0; kk < 16; kk++) {
            uint4 a0 = A[(size_t)kk * 128];
            uint4 a1 = A[(size_t)kk * 128 + 32];
            int k = kq * 16 + kk;
            uint4 b0 = smemB[k * 32 + lane];
            uint4 b1 = smemB[4096 + k * 32 + lane];
            mma8(acc[0][0][0], a0, b0.x, b0.y); mma8(acc[0][0][1], a0, b0.z, b0.w);
            mma8(acc[0][1][0], a0, b1.x, b1.y); mma8(acc[0][1][1], a0, b1.z, b1.w);
            mma8(acc[1][0][0], a1, b0.x, b0.y); mma8(acc[1][0][1], a1, b0.z, b0.w);
            mma8(acc[1][1][0], a1, b1.x, b1.y); mma8(acc[1][1][1], a1, b1.z, b1.w);
        }
#pragma unroll
        for (int a = 0; a < 2; a++)
#pragma unroll
            for (int nb = 0; nb < 2; nb++)
#pragma unroll
                for (int tn = 0; tn < 2; tn++) {
                    int rb = mh * 32 + a * 16 + g;
                    int cb = nb * 16 + tn * 8 + 2 * tg;
                    PS(kq, cb, rb)         = acc[a][nb][tn][0];
                    PS(kq, cb + 1, rb)     = acc[a][nb][tn][1];
                    PS(kq, cb, rb + 8)     = acc[a][nb][tn][2];
                    PS(kq, cb + 1, rb + 8) = acc[a][nb][tn][3];
                }
        __syncthreads();

        // epilogue: 1 cell per thread, sum 8 kq partials
        {
            float p[4];
#pragma unroll
            for (int gg = 0; gg < 4; gg++) {
                int pcl = gg * 8 + r_ep;
                float s = PS(0, pcl, b_ep);
#pragma unroll
                for (int q = 1; q < 8; q++) s += PS(q, pcl, b_ep);
                p[gg] = s + gxr[gg];
            }
            float ff = sigf(p[0]), ii = sigf(p[1]), uu = tanhf(p[2]), oo = sigf(p[3]);
            float cn = c_s[tid] * ff + ii * uu;
            c_s[tid] = cn;
            float h = oo * tanhf(cn);
            hbuf[tid * 9 + (t & 7)] = h;
            float* hAn = (float*)g_hA[par ^ 1];
            int lane2 = (b_ep & 7) * 4 + (r_ep & 3);
            int slot  = ((r_ep >> 2) & 1) * 2 + ((b_ep >> 3) & 1);
            int mtile = b_ep >> 4;
            hAn[(size_t)(jj * 128 + mtile * 32 + lane2) * 4 + slot] = tf32r(h);
        }

        // split barrier: arrive, then flush (overlaps other CTAs' arrival), then wait
        __threadfence();
        __syncthreads();
        if (tid == 0) atomicAdd(&g_arrive, 1u);

        if ((t & 7) == 7) {
            int t0 = t - 7;
            const float* src = &hbuf[tid * 9];
            float* dst = out + ((size_t)b_ep * HH + jj * 8 + r_ep) * TT + t0;
#pragma unroll
            for (int q = 0; q < 2; q++) {
                float4 v = make_float4(src[4 * q], src[4 * q + 1], src[4 * q + 2], src[4 * q + 3]);
                *(float4*)(dst + 4 * q) = v;
            }
        }

        if (tid == 0) {
            unsigned target = 128u * (unsigned)(t + 1);
            while (*(volatile unsigned*)&g_arrive < target) { }
            __threadfence();
        }
        __syncthreads();
    }

    // c_fin -> out tail
    out[(size_t)TB * HH * TT + b_ep * HH + jj * 8 + r_ep] = c_s[tid];
#undef PS
}

// ---------------- launch ----------------
extern "C" void kernel_launch(void* const* d_in, const int* in_sizes, int n_in,
                              void* d_out, int out_size) {
    const float* x   = (const float*)d_in[0];
    const float* y   = (const float*)d_in[1];
    // d_in[2] = subject_id (unused in 'none' mode)
    const float* Wf  = (const float*)d_in[3];
    const float* bf_ = (const float*)d_in[4];
    const float* Wi  = (const float*)d_in[5];
    const float* bi  = (const float*)d_in[6];
    const float* Wu  = (const float*)d_in[7];
    const float* bu  = (const float*)d_in[8];
    const float* Wo  = (const float*)d_in[9];
    const float* bo  = (const float*)d_in[10];
    float* out = (float*)d_out;

    // dynamic smem: Wh 131072 + hbuf 18432 + Ps 69632 + c_s 2048 = 221184 B
    const int P2_SMEM = 131072 + 512 * 9 * 4 + 8 * 32 * 68 * 4 + 512 * 4;
    cudaFuncSetAttribute(lstm_persist, cudaFuncAttributeMaxDynamicSharedMemorySize, P2_SMEM);

    prep_whB <<<16384, 256>>>(Wf, Wi, Wu, Wo);
    prep_wxB <<<8192, 256>>>(Wf, Wi, Wu, Wo);
    prep_xinA<<<8192, 256>>>(x, y);
    prep_misc<<<256, 256>>>(bf_, bi, bu, bo);

    p1_mma<<<dim3(32, 512), 256>>>();

    lstm_persist<<<128, 512, P2_SMEM>>>(out);
}

// round 16
// speedup vs baseline: 1.4411x; 1.1613x over previous
#include <cuda_runtime.h>
#include <cuda_bf16.h>
#include <cuda_fp16.h>
#include <cstdint>

#define TB 64
#define FF 256
#define TT 512
#define HH 1024

// Column packing: (g, n) with n = jj*8 + r  ->  PC = jj*32 + g*8 + r.
// P2 CTA jj (0..127) owns PC in [32jj, 32jj+32) = all 4 gates for n in [8jj, 8jj+8).

// ---------------- device scratch ----------------
__device__ uint2 g_hAh [2][16384];          // h A-frags ping-pong, fp16x2-packed: 4 halves per frag-lane
__device__ uint4 g_xinA[4194304];           // xin A-frags: idx4 = ((t*64 + k8)*4 + mtile)*32 + lane
__device__ uint4 g_WhB [1048576];           // Wh B-frags: idx4 = (nblk*128 + k8)*32 + lane (nblk = jj*2+nbw)
__device__ uint4 g_WxB [524288];            // Wx B-frags: idx4 = (nblk*64  + k8)*32 + lane
__device__ float g_bt  [4096];              // bias in PC order
__device__ float g_gx  [(size_t)TT * 4096 * 64];   // P1 out: [t][PC][b]
__device__ unsigned g_arrive;                      // grid-barrier counter (reset each launch)

__device__ __forceinline__ float tf32r(float v) {
    uint32_t r;
    asm("cvt.rna.tf32.f32 %0, %1;" : "=r"(r) : "f"(v));
    return __uint_as_float(r);
}
__device__ __forceinline__ float sigf(float x) { return 1.0f / (1.0f + __expf(-x)); }
// fast tanh: 1 - 2/(e^{2x}+1); saturates correctly (e->inf => 1, e->0 => -1)
__device__ __forceinline__ float tanhf_fast(float x) {
    float e = __expf(2.0f * x);
    return 1.0f - 2.0f / (e + 1.0f);
}

__device__ __forceinline__ void mma8(float* c, const uint4& a, uint32_t b0, uint32_t b1) {
    asm volatile("mma.sync.aligned.m16n8k8.row.col.f32.tf32.tf32.f32 "
                 "{%0,%1,%2,%3}, {%4,%5,%6,%7}, {%8,%9}, {%0,%1,%2,%3};"
                 : "+f"(c[0]), "+f"(c[1]), "+f"(c[2]), "+f"(c[3])
                 : "r"(a.x), "r"(a.y), "r"(a.z), "r"(a.w), "r"(b0), "r"(b1));
}

// unpack fp16x4 fragment -> 4 fp32 b32 regs (exact: fp16 mantissa fits tf32)
__device__ __forceinline__ uint4 h4_to_frag(uint2 p) {
    __half2 h01 = *reinterpret_cast<__half2*>(&p.x);
    __half2 h23 = *reinterpret_cast<__half2*>(&p.y);
    float2 f01 = __half22float2(h01);
    float2 f23 = __half22float2(h23);
    return make_uint4(__float_as_uint(f01.x), __float_as_uint(f01.y),
                      __float_as_uint(f23.x), __float_as_uint(f23.y));
}

// Fragment layouts (PTX m16n8k8): A lane=(row&7)*4+(col&3), slot=((col>>2)&1)*2+((row>>3)&1);
// B lane=n*4+(k&3), float4={t0b0,t0b1,t1b0,t1b1} per n16; C cols 2*tg+{0,1}, rows g/g+8.

// ---------------- prep: Wh -> B-fragments ----------------
__global__ __launch_bounds__(256) void prep_whB(const float* __restrict__ Wf, const float* __restrict__ Wi,
                                                const float* __restrict__ Wu, const float* __restrict__ Wo) {
    int gid = blockIdx.x * 256 + threadIdx.x;
    int n = gid & 1023, g = (gid >> 10) & 3, k = gid >> 12;
    const float* W = (g == 0) ? Wf : (g == 1) ? Wi : (g == 2) ? Wu : Wo;
    float v = tf32r(W[(size_t)(512 + k) * HH + n]);
    int jj = n >> 3, r = n & 7;
    int PC = jj * 32 + g * 8 + r;
    int nblk = PC >> 4, pcc = PC & 15;
    int tile = pcc >> 3, gg = pcc & 7;
    int lane = gg * 4 + (k & 3);
    int slot = tile * 2 + ((k >> 2) & 1);
    ((float*)g_WhB)[(size_t)(((nblk * 128) + (k >> 3)) * 32 + lane) * 4 + slot] = v;
}

// ---------------- prep: Wx -> B-fragments ----------------
__global__ __launch_bounds__(256) void prep_wxB(const float* __restrict__ Wf, const float* __restrict__ Wi,
                                                const float* __restrict__ Wu, const float* __restrict__ Wo) {
    int gid = blockIdx.x * 256 + threadIdx.x;
    int n = gid & 1023, g = (gid >> 10) & 3, k = gid >> 12;
    const float* W = (g == 0) ? Wf : (g == 1) ? Wi : (g == 2) ? Wu : Wo;
    float v = tf32r(W[(size_t)k * HH + n]);
    int jj = n >> 3, r = n & 7;
    int PC = jj * 32 + g * 8 + r;
    int nblk = PC >> 4, pcc = PC & 15;
    int tile = pcc >> 3, gg = pcc & 7;
    int lane = gg * 4 + (k & 3);
    int slot = tile * 2 + ((k >> 2) & 1);
    ((float*)g_WxB)[(size_t)(((nblk * 64) + (k >> 3)) * 32 + lane) * 4 + slot] = v;
}

// ---------------- prep: xin -> A-fragments ----------------
__global__ __launch_bounds__(256) void prep_xinA(const float* __restrict__ x, const float* __restrict__ y) {
    int gid = blockIdx.x * 256 + threadIdx.x;
    int k8 = gid & 63, b = (gid >> 6) & 63, t = gid >> 12;
    int mtile = b >> 4;
    size_t base4 = (size_t)(((t * 64 + k8) * 4) + mtile) * 32;
#pragma unroll
    for (int i = 0; i < 8; i++) {
        int kk = k8 * 8 + i;
        int f = kk >> 1;
        float v = (kk & 1) ? ((t > 0) ? y[(size_t)(b * FF + f) * TT + t - 1] : 0.0f)
                           : x[(size_t)(b * FF + f) * TT + t];
        int lane = (b & 7) * 4 + (kk & 3);
        int slot = ((kk >> 2) & 1) * 2 + ((b >> 3) & 1);
        ((float*)g_xinA)[(base4 + lane) * 4 + slot] = tf32r(v);
    }
}

// ---------------- prep: bias, zero h-frags, reset barrier ----------------
__global__ __launch_bounds__(256) void prep_misc(const float* __restrict__ bf_, const float* __restrict__ bi,
                                                 const float* __restrict__ bu, const float* __restrict__ bo) {
    int gid = blockIdx.x * 256 + threadIdx.x;
    if (gid == 0) g_arrive = 0u;
    if (gid < 16384) g_hAh[0][gid] = make_uint2(0, 0);
    if (gid < 4096) {
        int jj = gid >> 5, w5 = gid & 31;
        int g = w5 >> 3, r = w5 & 7;
        const float* bb = (g == 0) ? bf_ : (g == 1) ? bi : (g == 2) ? bu : bo;
        g_bt[gid] = bb[jj * 8 + r];
    }
}

// ---------------- P1: gx = xin @ Wx + b.  grid (32, 512), 256 thr ----------------
__global__ __launch_bounds__(256) void p1_mma() {
    __shared__ float Ps[128][66];
    const int tid = threadIdx.x, w = tid >> 5, lane = tid & 31;
    const int j1 = blockIdx.x, t = blockIdx.y;
    const int mi = w & 1, nw = w >> 1;
    float acc[2][4][4];
#pragma unroll
    for (int a = 0; a < 2; a++)
#pragma unroll
        for (int bq = 0; bq < 4; bq++)
#pragma unroll
            for (int cq = 0; cq < 4; cq++) acc[a][bq][cq] = 0.0f;

    const size_t aBase = (size_t)t * 64 * 128 + mi * 64 + lane;
    const size_t b0Base = (size_t)(j1 * 8 + nw * 2) * 64 * 32 + lane;
    const size_t b1Base = b0Base + (size_t)64 * 32;
#pragma unroll 2
    for (int k = 0; k < 64; k++) {
        uint4 a0 = g_xinA[aBase + k * 128];
        uint4 a1 = g_xinA[aBase + k * 128 + 32];
        uint4 b0 = g_WxB[b0Base + k * 32];
        uint4 b1 = g_WxB[b1Base + k * 32];
        mma8(acc[0][0], a0, b0.x, b0.y); mma8(acc[0][1], a0, b0.z, b0.w);
        mma8(acc[0][2], a0, b1.x, b1.y); mma8(acc[0][3], a0, b1.z, b1.w);
        mma8(acc[1][0], a1, b0.x, b0.y); mma8(acc[1][1], a1, b0.z, b0.w);
        mma8(acc[1][2], a1, b1.x, b1.y); mma8(acc[1][3], a1, b1.z, b1.w);
    }
    const int g = lane >> 2, tg = lane & 3;
#pragma unroll
    for (int tm = 0; tm < 2; tm++)
#pragma unroll
        for (int tn = 0; tn < 4; tn++) {
            int rb = mi * 32 + tm * 16 + g;
            int cb = nw * 32 + tn * 8 + 2 * tg;
            Ps[cb][rb]         = acc[tm][tn][0];
            Ps[cb + 1][rb]     = acc[tm][tn][1];
            Ps[cb][rb + 8]     = acc[tm][tn][2];
            Ps[cb + 1][rb + 8] = acc[tm][tn][3];
        }
    __syncthreads();
    float* gxp = g_gx + ((size_t)t * 4096 + j1 * 128) * 64;
    for (int i = tid; i < 8192; i += 256) {
        int pcl = i >> 6, b = i & 63;
        gxp[(size_t)pcl * 64 + b] = Ps[pcl][b] + g_bt[j1 * 128 + pcl];
    }
}

// ---------------- P2: persistent LSTM. grid 128, 512 thr (16 warps) ----------------
// Warp (kq 0..7, mh 0..1): K-eighth x m32. h A-image stored fp16x2-packed (halves L2 traffic).
// Dynamic smem: [0,8192) uint4 Wh; hbuf 512*9 f32; Ps 8*32*68 f32; c_s 512 f32.
__global__ __launch_bounds__(512) void lstm_persist(float* __restrict__ out) {
    extern __shared__ uint4 smemB[];
    float* hbuf = (float*)(smemB + 8192);               // 512*9  = 4608 f32
    float* PsF  = hbuf + 512 * 9;                       // 8*32*68 = 17408 f32
    float* c_s  = PsF + 8 * 32 * 68;                    // 512 f32
#define PS(q, c, r) PsF[((q) * 32 + (c)) * 68 + (r)]
    const int tid = threadIdx.x, w = tid >> 5, lane = tid & 31;
    const int jj = blockIdx.x;
    const int kq = w & 7, mh = w >> 3;
    const int g = lane >> 2, tg = lane & 3;
    const int r_ep = tid >> 6, b_ep = tid & 63;    // epilogue cell (1 per thread)

    {   // load Wh slice into smem once
        const uint4* src = g_WhB + (size_t)jj * 8192;
        for (int i = tid; i < 8192; i += 512) smemB[i] = src[i];
    }
    c_s[tid] = 0.0f;
    __syncthreads();

    for (int t = 0; t < TT; t++) {
        const int par = t & 1;
        float gxr[4];
        const float* gxp = g_gx + ((size_t)t * 4096 + jj * 32) * 64;
#pragma unroll
        for (int i = 0; i < 4; i++) gxr[i] = gxp[tid + i * 512];   // gx[gg*512 + tid]

        float acc[2][2][2][4];      // [a-tile][nb][tn][4]
#pragma unroll
        for (int a = 0; a < 2; a++)
#pragma unroll
            for (int nb = 0; nb < 2; nb++)
#pragma unroll
                for (int tn = 0; tn < 2; tn++)
#pragma unroll
                    for (int cq = 0; cq < 4; cq++) acc[a][nb][tn][cq] = 0.0f;

        const uint2* __restrict__ A = g_hAh[par] + (size_t)(kq * 16) * 128 + mh * 64 + lane;
#pragma unroll 4
        for (int kk = 0; kk < 16; kk++) {
            uint4 a0 = h4_to_frag(A[(size_t)kk * 128]);
            uint4 a1 = h4_to_frag(A[(size_t)kk * 128 + 32]);
            int k = kq * 16 + kk;
            uint4 b0 = smemB[k * 32 + lane];
            uint4 b1 = smemB[4096 + k * 32 + lane];
            mma8(acc[0][0][0], a0, b0.x, b0.y); mma8(acc[0][0][1], a0, b0.z, b0.w);
            mma8(acc[0][1][0], a0, b1.x, b1.y); mma8(acc[0][1][1], a0, b1.z, b1.w);
            mma8(acc[1][0][0], a1, b0.x, b0.y); mma8(acc[1][0][1], a1, b0.z, b0.w);
            mma8(acc[1][1][0], a1, b1.x, b1.y); mma8(acc[1][1][1], a1, b1.z, b1.w);
        }
#pragma unroll
        for (int a = 0; a < 2; a++)
#pragma unroll
            for (int nb = 0; nb < 2; nb++)
#pragma unroll
                for (int tn = 0; tn < 2; tn++) {
                    int rb = mh * 32 + a * 16 + g;
                    int cb = nb * 16 + tn * 8 + 2 * tg;
                    PS(kq, cb, rb)         = acc[a][nb][tn][0];
                    PS(kq, cb + 1, rb)     = acc[a][nb][tn][1];
                    PS(kq, cb, rb + 8)     = acc[a][nb][tn][2];
                    PS(kq, cb + 1, rb + 8) = acc[a][nb][tn][3];
                }
        __syncthreads();

        // epilogue: 1 cell per thread, sum 8 kq partials
        {
            float p[4];
#pragma unroll
            for (int gg = 0; gg < 4; gg++) {
                int pcl = gg * 8 + r_ep;
                float s = PS(0, pcl, b_ep);
#pragma unroll
                for (int q = 1; q < 8; q++) s += PS(q, pcl, b_ep);
                p[gg] = s + gxr[gg];
            }
            float ff = sigf(p[0]), ii = sigf(p[1]), uu = tanhf_fast(p[2]), oo = sigf(p[3]);
            float cn = c_s[tid] * ff + ii * uu;
            c_s[tid] = cn;
            float h = oo * tanhf_fast(cn);
            hbuf[tid * 9 + (t & 7)] = h;
            // write h (fp16) into next step's packed A-image
            __half* hAn = (__half*)g_hAh[par ^ 1];
            int lane2 = (b_ep & 7) * 4 + (r_ep & 3);
            int slot  = ((r_ep >> 2) & 1) * 2 + ((b_ep >> 3) & 1);
            int mtile = b_ep >> 4;
            hAn[(size_t)(jj * 128 + mtile * 32 + lane2) * 4 + slot] = __float2half(h);
        }

        // split barrier: arrive, then flush (overlaps other CTAs' arrival), then wait
        __threadfence();
        __syncthreads();
        if (tid == 0) atomicAdd(&g_arrive, 1u);

        if ((t & 7) == 7) {
            int t0 = t - 7;
            const float* src = &hbuf[tid * 9];
            float* dst = out + ((size_t)b_ep * HH + jj * 8 + r_ep) * TT + t0;
#pragma unroll
            for (int q = 0; q < 2; q++) {
                float4 v = make_float4(src[4 * q], src[4 * q + 1], src[4 * q + 2], src[4 * q + 3]);
                *(float4*)(dst + 4 * q) = v;
            }
        }

        if (tid == 0) {
            unsigned target = 128u * (unsigned)(t + 1);
            while (*(volatile unsigned*)&g_arrive < target) { }
            __threadfence();
        }
        __syncthreads();
    }

    // c_fin -> out tail
    out[(size_t)TB * HH * TT + b_ep * HH + jj * 8 + r_ep] = c_s[tid];
#undef PS
}

// ---------------- launch ----------------
extern "C" void kernel_launch(void* const* d_in, const int* in_sizes, int n_in,
                              void* d_out, int out_size) {
    const float* x   = (const float*)d_in[0];
    const float* y   = (const float*)d_in[1];
    // d_in[2] = subject_id (unused in 'none' mode)
    const float* Wf  = (const float*)d_in[3];
    const float* bf_ = (const float*)d_in[4];
    const float* Wi  = (const float*)d_in[5];
    const float* bi  = (const float*)d_in[6];
    const float* Wu  = (const float*)d_in[7];
    const float* bu  = (const float*)d_in[8];
    const float* Wo  = (const float*)d_in[9];
    const float* bo  = (const float*)d_in[10];
    float* out = (float*)d_out;

    // dynamic smem: Wh 131072 + hbuf 18432 + Ps 69632 + c_s 2048 = 221184 B
    const int P2_SMEM = 131072 + 512 * 9 * 4 + 8 * 32 * 68 * 4 + 512 * 4;
    cudaFuncSetAttribute(lstm_persist, cudaFuncAttributeMaxDynamicSharedMemorySize, P2_SMEM);

    prep_whB <<<16384, 256>>>(Wf, Wi, Wu, Wo);
    prep_wxB <<<8192, 256>>>(Wf, Wi, Wu, Wo);
    prep_xinA<<<8192, 256>>>(x, y);
    prep_misc<<<256, 256>>>(bf_, bi, bu, bo);

    p1_mma<<<dim3(32, 512), 256>>>();

    lstm_persist<<<128, 512, P2_SMEM>>>(out);
}

// round 17
// speedup vs baseline: 1.5560x; 1.0798x over previous
#include <cuda_runtime.h>
#include <cuda_bf16.h>
#include <cuda_fp16.h>
#include <cstdint>

#define TB 64
#define FF 256
#define TT 512
#define HH 1024

// Column packing: (g, n) with n = jj*8 + r  ->  PC = jj*32 + g*8 + r.
// P2 CTA jj (0..127) owns PC in [32jj, 32jj+32) = all 4 gates for n in [8jj, 8jj+8).

// ---------------- device scratch ----------------
__device__ uint4 g_hA16[2][8192];           // h A-frags (m16n8k16 fp16): idx4 = (kc*4 + mtile)*32 + lane
__device__ uint4 g_xinA[4194304];           // xin A-frags (tf32, P1): idx4 = ((t*64 + k8)*4 + mtile)*32 + lane
__device__ uint2 g_WhB16[1048576];          // Wh B-frags fp16: idx2 = ((jj*4 + gate)*64 + kc)*32 + lane  (8MB)
__device__ uint4 g_WxB [524288];            // Wx B-frags (tf32, P1)
__device__ float g_bt  [4096];              // bias in PC order
__device__ float g_gx  [(size_t)TT * 4096 * 64];   // P1 out: [t][PC][b]
__device__ unsigned g_arrive;                      // grid-barrier counter (reset each launch)

__device__ __forceinline__ float tf32r(float v) {
    uint32_t r;
    asm("cvt.rna.tf32.f32 %0, %1;" : "=r"(r) : "f"(v));
    return __uint_as_float(r);
}
__device__ __forceinline__ float sigf(float x) { return 1.0f / (1.0f + __expf(-x)); }
// fast tanh: 1 - 2/(e^{2x}+1); saturates correctly
__device__ __forceinline__ float tanhf_fast(float x) {
    float e = __expf(2.0f * x);
    return 1.0f - 2.0f / (e + 1.0f);
}

// tf32 m16n8k8 (P1)
__device__ __forceinline__ void mma8(float* c, const uint4& a, uint32_t b0, uint32_t b1) {
    asm volatile("mma.sync.aligned.m16n8k8.row.col.f32.tf32.tf32.f32 "
                 "{%0,%1,%2,%3}, {%4,%5,%6,%7}, {%8,%9}, {%0,%1,%2,%3};"
                 : "+f"(c[0]), "+f"(c[1]), "+f"(c[2]), "+f"(c[3])
                 : "r"(a.x), "r"(a.y), "r"(a.z), "r"(a.w), "r"(b0), "r"(b1));
}
// fp16 m16n8k16, fp32 accumulate (P2)
__device__ __forceinline__ void mma16(float* c, const uint4& a, const uint2& b) {
    asm volatile("mma.sync.aligned.m16n8k16.row.col.f32.f16.f16.f32 "
                 "{%0,%1,%2,%3}, {%4,%5,%6,%7}, {%8,%9}, {%0,%1,%2,%3};"
                 : "+f"(c[0]), "+f"(c[1]), "+f"(c[2]), "+f"(c[3])
                 : "r"(a.x), "r"(a.y), "r"(a.z), "r"(a.w), "r"(b.x), "r"(b.y));
}

// m16n8k16 fp16 layouts (PTX ISA):
// A(16x16): lane=(row&7)*4+((k&7)>>1); reg=((k>>3)&1)*2+((row>>3)&1); halfpos=k&1
// B(16x8):  lane=(n&7)*4+((k&7)>>1);  reg=(k>>3)&1;                   halfpos=k&1
// C: c0,c1=(row g, cols 2tg+{0,1}); c2,c3=(row g+8, same cols)

// ---------------- prep: Wh -> fp16 B-fragments ----------------
__global__ __launch_bounds__(256) void prep_whB(const float* __restrict__ Wf, const float* __restrict__ Wi,
                                                const float* __restrict__ Wu, const float* __restrict__ Wo) {
    int gid = blockIdx.x * 256 + threadIdx.x;       // k*4096 + gate*1024 + n ; 1024*4096
    int n = gid & 1023, gate = (gid >> 10) & 3, k = gid >> 12;
    const float* W = (gate == 0) ? Wf : (gate == 1) ? Wi : (gate == 2) ? Wu : Wo;
    float v = W[(size_t)(512 + k) * HH + n];
    int jj = n >> 3, r = n & 7;
    int lane = r * 4 + ((k & 7) >> 1);
    int reg  = (k >> 3) & 1;
    int hp   = k & 1;
    size_t idx2 = (((size_t)jj * 4 + gate) * 64 + (k >> 4)) * 32 + lane;
    ((__half*)g_WhB16)[idx2 * 4 + reg * 2 + hp] = __float2half(v);
}

// ---------------- prep: Wx -> tf32 B-fragments (P1) ----------------
__global__ __launch_bounds__(256) void prep_wxB(const float* __restrict__ Wf, const float* __restrict__ Wi,
                                                const float* __restrict__ Wu, const float* __restrict__ Wo) {
    int gid = blockIdx.x * 256 + threadIdx.x;
    int n = gid & 1023, g = (gid >> 10) & 3, k = gid >> 12;
    const float* W = (g == 0) ? Wf : (g == 1) ? Wi : (g == 2) ? Wu : Wo;
    float v = tf32r(W[(size_t)k * HH + n]);
    int jj = n >> 3, r = n & 7;
    int PC = jj * 32 + g * 8 + r;
    int nblk = PC >> 4, pcc = PC & 15;
    int tile = pcc >> 3, gg = pcc & 7;
    int lane = gg * 4 + (k & 3);
    int slot = tile * 2 + ((k >> 2) & 1);
    ((float*)g_WxB)[(size_t)(((nblk * 64) + (k >> 3)) * 32 + lane) * 4 + slot] = v;
}

// ---------------- prep: xin -> tf32 A-fragments (P1) ----------------
__global__ __launch_bounds__(256) void prep_xinA(const float* __restrict__ x, const float* __restrict__ y) {
    int gid = blockIdx.x * 256 + threadIdx.x;
    int k8 = gid & 63, b = (gid >> 6) & 63, t = gid >> 12;
    int mtile = b >> 4;
    size_t base4 = (size_t)(((t * 64 + k8) * 4) + mtile) * 32;
#pragma unroll
    for (int i = 0; i < 8; i++) {
        int kk = k8 * 8 + i;
        int f = kk >> 1;
        float v = (kk & 1) ? ((t > 0) ? y[(size_t)(b * FF + f) * TT + t - 1] : 0.0f)
                           : x[(size_t)(b * FF + f) * TT + t];
        int lane = (b & 7) * 4 + (kk & 3);
        int slot = ((kk >> 2) & 1) * 2 + ((b >> 3) & 1);
        ((float*)g_xinA)[(base4 + lane) * 4 + slot] = tf32r(v);
    }
}

// ---------------- prep: bias, zero h-frags, reset barrier ----------------
__global__ __launch_bounds__(256) void prep_misc(const float* __restrict__ bf_, const float* __restrict__ bi,
                                                 const float* __restrict__ bu, const float* __restrict__ bo) {
    int gid = blockIdx.x * 256 + threadIdx.x;
    if (gid == 0) g_arrive = 0u;
    if (gid < 8192) g_hA16[0][gid] = make_uint4(0, 0, 0, 0);
    if (gid < 4096) {
        int jj = gid >> 5, w5 = gid & 31;
        int g = w5 >> 3, r = w5 & 7;
        const float* bb = (g == 0) ? bf_ : (g == 1) ? bi : (g == 2) ? bu : bo;
        g_bt[gid] = bb[jj * 8 + r];
    }
}

// ---------------- P1: gx = xin @ Wx + b.  grid (32, 512), 256 thr ----------------
__global__ __launch_bounds__(256) void p1_mma() {
    __shared__ float Ps[128][66];
    const int tid = threadIdx.x, w = tid >> 5, lane = tid & 31;
    const int j1 = blockIdx.x, t = blockIdx.y;
    const int mi = w & 1, nw = w >> 1;
    float acc[2][4][4];
#pragma unroll
    for (int a = 0; a < 2; a++)
#pragma unroll
        for (int bq = 0; bq < 4; bq++)
#pragma unroll
            for (int cq = 0; cq < 4; cq++) acc[a][bq][cq] = 0.0f;

    const size_t aBase = (size_t)t * 64 * 128 + mi * 64 + lane;
    const size_t b0Base = (size_t)(j1 * 8 + nw * 2) * 64 * 32 + lane;
    const size_t b1Base = b0Base + (size_t)64 * 32;
#pragma unroll 2
    for (int k = 0; k < 64; k++) {
        uint4 a0 = g_xinA[aBase + k * 128];
        uint4 a1 = g_xinA[aBase + k * 128 + 32];
        uint4 b0 = g_WxB[b0Base + k * 32];
        uint4 b1 = g_WxB[b1Base + k * 32];
        mma8(acc[0][0], a0, b0.x, b0.y); mma8(acc[0][1], a0, b0.z, b0.w);
        mma8(acc[0][2], a0, b1.x, b1.y); mma8(acc[0][3], a0, b1.z, b1.w);
        mma8(acc[1][0], a1, b0.x, b0.y); mma8(acc[1][1], a1, b0.z, b0.w);
        mma8(acc[1][2], a1, b1.x, b1.y); mma8(acc[1][3], a1, b1.z, b1.w);
    }
    const int g = lane >> 2, tg = lane & 3;
#pragma unroll
    for (int tm = 0; tm < 2; tm++)
#pragma unroll
        for (int tn = 0; tn < 4; tn++) {
            int rb = mi * 32 + tm * 16 + g;
            int cb = nw * 32 + tn * 8 + 2 * tg;
            Ps[cb][rb]         = acc[tm][tn][0];
            Ps[cb + 1][rb]     = acc[tm][tn][1];
            Ps[cb][rb + 8]     = acc[tm][tn][2];
            Ps[cb + 1][rb + 8] = acc[tm][tn][3];
        }
    __syncthreads();
    float* gxp = g_gx + ((size_t)t * 4096 + j1 * 128) * 64;
    for (int i = tid; i < 8192; i += 256) {
        int pcl = i >> 6, b = i & 63;
        gxp[(size_t)pcl * 64 + b] = Ps[pcl][b] + g_bt[j1 * 128 + pcl];
    }
}

// ---------------- P2: persistent LSTM. grid 128, 512 thr (16 warps) ----------------
// fp16 m16n8k16 MMA. Warp (kq 0..7, mh 0..1): 8 k16-chunks x m32, full n32 (4 n8-tiles).
// Dynamic smem (uint2 base): [0,8192) Wh fp16 (64KB); hbuf 512*9 f32; Ps 8*32*68 f32; c_s 512 f32.
__global__ __launch_bounds__(512) void lstm_persist(float* __restrict__ out) {
    extern __shared__ uint2 smemB[];
    float* hbuf = (float*)(smemB + 8192);               // 512*9  = 4608 f32
    float* PsF  = hbuf + 512 * 9;                       // 8*32*68 = 17408 f32
    float* c_s  = PsF + 8 * 32 * 68;                    // 512 f32
#define PS(q, c, r) PsF[((q) * 32 + (c)) * 68 + (r)]
    const int tid = threadIdx.x, w = tid >> 5, lane = tid & 31;
    const int jj = blockIdx.x;
    const int kq = w & 7, mh = w >> 3;
    const int g = lane >> 2, tg = lane & 3;
    const int r_ep = tid >> 6, b_ep = tid & 63;    // epilogue cell (1 per thread)

    {   // load fp16 Wh slice into smem once: [(gate*64 + kc)*32 + lane]
        const uint2* src = g_WhB16 + (size_t)jj * 8192;
        for (int i = tid; i < 8192; i += 512) smemB[i] = src[i];
    }
    c_s[tid] = 0.0f;
    __syncthreads();

    for (int t = 0; t < TT; t++) {
        const int par = t & 1;
        float gxr[4];
        const float* gxp = g_gx + ((size_t)t * 4096 + jj * 32) * 64;
#pragma unroll
        for (int i = 0; i < 4; i++) gxr[i] = gxp[tid + i * 512];   // gx[gg*512 + tid]

        float acc[2][4][4];         // [a-tile][n8-tile][4]
#pragma unroll
        for (int a = 0; a < 2; a++)
#pragma unroll
            for (int nb = 0; nb < 4; nb++)
#pragma unroll
                for (int cq = 0; cq < 4; cq++) acc[a][nb][cq] = 0.0f;

        const uint4* __restrict__ A = g_hA16[par];
#pragma unroll 4
        for (int i = 0; i < 8; i++) {
            int c = kq * 8 + i;     // k16-chunk 0..63
            uint4 a0 = A[(size_t)(c * 4 + mh * 2) * 32 + lane];
            uint4 a1 = A[(size_t)(c * 4 + mh * 2 + 1) * 32 + lane];
            uint2 b0 = smemB[(0 * 64 + c) * 32 + lane];
            uint2 b1 = smemB[(1 * 64 + c) * 32 + lane];
            uint2 b2 = smemB[(2 * 64 + c) * 32 + lane];
            uint2 b3 = smemB[(3 * 64 + c) * 32 + lane];
            mma16(acc[0][0], a0, b0); mma16(acc[0][1], a0, b1);
            mma16(acc[0][2], a0, b2); mma16(acc[0][3], a0, b3);
            mma16(acc[1][0], a1, b0); mma16(acc[1][1], a1, b1);
            mma16(acc[1][2], a1, b2); mma16(acc[1][3], a1, b3);
        }
#pragma unroll
        for (int a = 0; a < 2; a++)
#pragma unroll
            for (int nb = 0; nb < 4; nb++) {
                int rb = mh * 32 + a * 16 + g;
                int cb = nb * 8 + 2 * tg;
                PS(kq, cb, rb)         = acc[a][nb][0];
                PS(kq, cb + 1, rb)     = acc[a][nb][1];
                PS(kq, cb, rb + 8)     = acc[a][nb][2];
                PS(kq, cb + 1, rb + 8) = acc[a][nb][3];
            }
        __syncthreads();

        // epilogue: 1 cell per thread, sum 8 kq partials
        {
            float p[4];
#pragma unroll
            for (int gg = 0; gg < 4; gg++) {
                int pcl = gg * 8 + r_ep;
                float s = PS(0, pcl, b_ep);
#pragma unroll
                for (int q = 1; q < 8; q++) s += PS(q, pcl, b_ep);
                p[gg] = s + gxr[gg];
            }
            float ff = sigf(p[0]), ii = sigf(p[1]), uu = tanhf_fast(p[2]), oo = sigf(p[3]);
            float cn = c_s[tid] * ff + ii * uu;
            c_s[tid] = cn;
            float h = oo * tanhf_fast(cn);
            hbuf[tid * 9 + (t & 7)] = h;
            // write h (fp16) into next step's m16n8k16 A-image: element (row=b, k=n)
            int n = jj * 8 + r_ep;
            int kc = n >> 4, k_in = n & 15;
            int row = b_ep & 15, mtile = b_ep >> 4;
            int lane2 = (row & 7) * 4 + ((k_in & 7) >> 1);
            int reg   = ((k_in >> 3) & 1) * 2 + ((row >> 3) & 1);
            int hp    = k_in & 1;
            __half* hAn = (__half*)g_hA16[par ^ 1];
            hAn[((size_t)(kc * 4 + mtile) * 32 + lane2) * 8 + reg * 2 + hp] = __float2half(h);
        }

        // split barrier: arrive, then flush (overlaps other CTAs' arrival), then wait
        __threadfence();
        __syncthreads();
        if (tid == 0) atomicAdd(&g_arrive, 1u);

        if ((t & 7) == 7) {
            int t0 = t - 7;
            const float* src = &hbuf[tid * 9];
            float* dst = out + ((size_t)b_ep * HH + jj * 8 + r_ep) * TT + t0;
#pragma unroll
            for (int q = 0; q < 2; q++) {
                float4 v = make_float4(src[4 * q], src[4 * q + 1], src[4 * q + 2], src[4 * q + 3]);
                *(float4*)(dst + 4 * q) = v;
            }
        }

        if (tid == 0) {
            unsigned target = 128u * (unsigned)(t + 1);
            while (*(volatile unsigned*)&g_arrive < target) { }
            __threadfence();
        }
        __syncthreads();
    }

    // c_fin -> out tail
    out[(size_t)TB * HH * TT + b_ep * HH + jj * 8 + r_ep] = c_s[tid];
#undef PS
}

// ---------------- launch ----------------
extern "C" void kernel_launch(void* const* d_in, const int* in_sizes, int n_in,
                              void* d_out, int out_size) {
    const float* x   = (const float*)d_in[0];
    const float* y   = (const float*)d_in[1];
    // d_in[2] = subject_id (unused in 'none' mode)
    const float* Wf  = (const float*)d_in[3];
    const float* bf_ = (const float*)d_in[4];
    const float* Wi  = (const float*)d_in[5];
    const float* bi  = (const float*)d_in[6];
    const float* Wu  = (const float*)d_in[7];
    const float* bu  = (const float*)d_in[8];
    const float* Wo  = (const float*)d_in[9];
    const float* bo  = (const float*)d_in[10];
    float* out = (float*)d_out;

    // dynamic smem: Wh fp16 65536 + hbuf 18432 + Ps 69632 + c_s 2048 = 155648 B
    const int P2_SMEM = 65536 + 512 * 9 * 4 + 8 * 32 * 68 * 4 + 512 * 4;
    cudaFuncSetAttribute(lstm_persist, cudaFuncAttributeMaxDynamicSharedMemorySize, P2_SMEM);

    prep_whB <<<16384, 256>>>(Wf, Wi, Wu, Wo);
    prep_wxB <<<8192, 256>>>(Wf, Wi, Wu, Wo);
    prep_xinA<<<8192, 256>>>(x, y);
    prep_misc<<<256, 256>>>(bf_, bi, bu, bo);

    p1_mma<<<dim3(32, 512), 256>>>();

    lstm_persist<<<128, 512, P2_SMEM>>>(out);
}